// round 7
// baseline (speedup 1.0000x reference)
#include <cuda_runtime.h>
#include <math.h>

// ROI pooling, single ROI, POOL = 7x7, SCALE_FACTOR = 1.0
// img: (1, 512, 512, 256) fp32 NHWC   -> d_in[0]
// roi: (1, 5) fp32 [_, x_min, y_min, x_max, y_max] -> d_in[1]
// out: (1, 256, 7, 7) fp32            -> d_out
//
// out[c*49 + py*7 + px] = img[((iy*512) + ix)*256 + c]
// iy = clip(y_min + floor(py * (h/7)), y_min, y_max), same for ix.
// Index math mirrors the JAX reference bit-exactly in fp32:
//   jnp.round -> rintf (round-half-to-even), h/7 in fp32, floorf.
//
// Kernel is launch-overhead bound (real data path: two dependent L2 hits,
// ~0.3us of work behind ~5.7us of fixed per-launch cost). This round
// collapses the grid 49 -> 7 CTAs (448 threads each: 7 pooled pixels x
// 64 float4 channel-groups) to remove the CTA-dispatch ramp term — the
// only term left that a kernel edit can touch.

#define IMG_COLS 512
#define IMG_C    256
#define PH 7
#define PW 7

__global__ __launch_bounds__(448)
void roi_pool_kernel(const float4* __restrict__ img4,
                     const float*  __restrict__ roi,
                     float* __restrict__ out)
{
    const int t  = threadIdx.x & 63;          // channel group 0..63 (4 ch each)
    const int p  = blockIdx.x * 7 + (threadIdx.x >> 6);  // pooled pixel 0..48
    const int py = p / PW;
    const int px = p % PW;

    // roi[0..3] is 16B-aligned -> one LDG.128, plus one scalar load.
    const float4 r03 = *(const float4*)roi;   // {_, x_min, y_min, x_max}
    const float  r4  = roi[4];                //  y_max

    const int x_min = (int)rintf(r03.y);
    const int y_min = (int)rintf(r03.z);
    const int x_max = (int)rintf(r03.w);
    const int y_max = (int)rintf(r4);

    const float h = (float)(y_max - y_min + 1);
    const float w = (float)(x_max - x_min + 1);

    int iy = y_min + (int)floorf((float)py * (h / 7.0f));
    int ix = x_min + (int)floorf((float)px * (w / 7.0f));
    iy = min(max(iy, y_min), y_max);
    ix = min(max(ix, x_min), x_max);

    // One 16B load per thread: each 64-thread slice reads its pixel's
    // full 1KB channel vector coalesced.
    const float4 v = img4[((iy * IMG_COLS) + ix) * (IMG_C / 4) + t];

    // NCHW output: out[c*49 + p]; c = 4*t .. 4*t+3. Scatter absorbed by L2.
    const int base = (4 * t) * (PH * PW) + p;
    out[base]               = v.x;
    out[base + PH * PW]     = v.y;
    out[base + 2 * PH * PW] = v.z;
    out[base + 3 * PH * PW] = v.w;
}

extern "C" void kernel_launch(void* const* d_in, const int* in_sizes, int n_in,
                              void* d_out, int out_size)
{
    const float4* img4 = (const float4*)d_in[0];
    const float*  roi  = (const float*)d_in[1];
    float* out = (float*)d_out;

    roi_pool_kernel<<<PH, 448>>>(img4, roi, out);
}

// round 8
// speedup vs baseline: 1.0829x; 1.0829x over previous
#include <cuda_runtime.h>
#include <math.h>

// ROI pooling, single ROI, POOL = 7x7, SCALE_FACTOR = 1.0
// img: (1, 512, 512, 256) fp32 NHWC   -> d_in[0]
// roi: (1, 5) fp32 [_, x_min, y_min, x_max, y_max] -> d_in[1]
// out: (1, 256, 7, 7) fp32            -> d_out
//
// out[c*49 + py*7 + px] = img[((iy*512) + ix)*256 + c]
// iy = clip(y_min + floor(py * (h/7)), y_min, y_max), same for ix.
// Index math mirrors the JAX reference bit-exactly in fp32:
//   jnp.round -> rintf (round-half-to-even), h/7 in fp32, floorf.
//
// Launch-overhead-bound kernel (~5.6us fixed + ~0.4us dependent
// roi->img L2 chain). R6 showed fewer/fatter CTAs REGRESS (7x448:
// +0.7us) — wide-and-shallow wins for a latency chain. This round:
// back to grid=49 (one CTA/pixel on 49 SMs), ONE warp per CTA.
// Each thread issues two independent float4 loads (MLP=2, second is
// latency-free) covering the pixel's 1KB channel vector coalesced.

#define IMG_COLS 512
#define IMG_C    256
#define PH 7
#define PW 7

__global__ __launch_bounds__(32)
void roi_pool_kernel(const float4* __restrict__ img4,
                     const float*  __restrict__ roi,
                     float* __restrict__ out)
{
    const int p  = blockIdx.x;        // pooled pixel 0..48
    const int py = p / PW;
    const int px = p % PW;
    const int t  = threadIdx.x;       // 0..31

    // roi[0..3] is 16B-aligned -> one LDG.128, plus one scalar load
    // (both issued back-to-back, independent).
    const float4 r03 = *(const float4*)roi;   // {_, x_min, y_min, x_max}
    const float  r4  = roi[4];                //  y_max

    const int x_min = (int)rintf(r03.y);
    const int y_min = (int)rintf(r03.z);
    const int x_max = (int)rintf(r03.w);
    const int y_max = (int)rintf(r4);

    const float h = (float)(y_max - y_min + 1);
    const float w = (float)(x_max - x_min + 1);

    int iy = y_min + (int)floorf((float)py * (h / 7.0f));
    int ix = x_min + (int)floorf((float)px * (w / 7.0f));
    iy = min(max(iy, y_min), y_max);
    ix = min(max(ix, x_min), x_max);

    // Two independent 16B loads per thread: 32 threads x 32B = the
    // pixel's full 1KB channel vector, coalesced, MLP=2.
    const int rowbase = ((iy * IMG_COLS) + ix) * (IMG_C / 4);
    const float4 v0 = img4[rowbase + t];        // channels 4t   .. 4t+3
    const float4 v1 = img4[rowbase + 32 + t];   // channels 128+4t .. 128+4t+3

    // NCHW output: out[c*49 + p]. Scatter absorbed by L2 (out = 50KB).
    const int b0 = (4 * t) * (PH * PW) + p;
    out[b0]                 = v0.x;
    out[b0 + PH * PW]       = v0.y;
    out[b0 + 2 * PH * PW]   = v0.z;
    out[b0 + 3 * PH * PW]   = v0.w;

    const int b1 = (128 + 4 * t) * (PH * PW) + p;
    out[b1]                 = v1.x;
    out[b1 + PH * PW]       = v1.y;
    out[b1 + 2 * PH * PW]   = v1.z;
    out[b1 + 3 * PH * PW]   = v1.w;
}

extern "C" void kernel_launch(void* const* d_in, const int* in_sizes, int n_in,
                              void* d_out, int out_size)
{
    const float4* img4 = (const float4*)d_in[0];
    const float*  roi  = (const float*)d_in[1];
    float* out = (float*)d_out;

    roi_pool_kernel<<<PH * PW, 32>>>(img4, roi, out);
}